// round 13
// baseline (speedup 1.0000x reference)
#include <cuda_runtime.h>
#include <cuda_fp16.h>
#include <cstdint>

#define BB 8
#define NN 1024
#define FIN 64
#define FOUT 128
#define HH 4
#define DD 32
#define TI 32
#define LOG2E 1.4426950408889634f

// device-global scratch. Transposed + permuted h: [b][f][j_perm], fp16.
// Within each 32-node group, slot s holds node j = 2*(s>>3) + (((s&7)>>1)<<3) + (s&1).
__device__ __align__(16) __half g_hT[BB * FOUT * NN];
__device__ float g_src[BB * NN * HH];           // pre-scaled by log2e
__device__ float g_dst[BB * NN * HH];
__device__ float g_lpart[2 * BB * NN * HH];     // partial softmax denominators
// q = exp(e)*mask*ew, fp16, fragment-permuted: [b][z][i-tile 32][h 4][i 32][512]
__device__ __align__(16) __half g_q[(size_t)BB * 2 * 32 * 4 * 32 * 512];

__device__ __forceinline__ float ex2f(float x) {
    float r;
    asm("ex2.approx.ftz.f32 %0, %1;" : "=f"(r) : "f"(x));
    return r;
}
__device__ __forceinline__ void mma16816(float* d, unsigned a0, unsigned a1,
                                         unsigned a2, unsigned a3,
                                         unsigned b0, unsigned b1) {
    asm volatile(
        "mma.sync.aligned.m16n8k16.row.col.f32.f16.f16.f32 "
        "{%0,%1,%2,%3},{%4,%5,%6,%7},{%8,%9},{%0,%1,%2,%3};"
        : "+f"(d[0]), "+f"(d[1]), "+f"(d[2]), "+f"(d[3])
        : "r"(a0), "r"(a1), "r"(a2), "r"(a3), "r"(b0), "r"(b1));
}

// ---------------- Kernel 1: h = x@W (f32x2, 2x4 register block, 256 thr) ----------------
// Unchanged from R12 (proven). Also zeroes `out`.
__global__ __launch_bounds__(256) void gat_k1(
    const float* __restrict__ x, const float* __restrict__ W, const float* __restrict__ a,
    float* __restrict__ out)
{
    __shared__ float sW[FIN * 68];
    __shared__ float sx[32 * 68];
    __shared__ __half sh[32 * 72];
    __shared__ float sa[HH * 2 * DD];

    int t     = threadIdx.x;
    int b     = blockIdx.x >> 6;
    int n0    = ((blockIdx.x >> 1) & 31) << 5;
    int fhalf = blockIdx.x & 1;

    {
        float4 z = make_float4(0.f, 0.f, 0.f, 0.f);
        size_t o4 = ((size_t)blockIdx.x * 256 + t) * 2;
        ((float4*)out)[o4]     = z;
        ((float4*)out)[o4 + 1] = z;
    }

    {
        const float4* W4 = (const float4*)W;
        #pragma unroll
        for (int s = 0; s < 4; s++) {
            int idx = t + (s << 8);
            int row = idx >> 4, c4 = idx & 15;
            *(float4*)(sW + row * 68 + (c4 << 2)) = W4[(row << 5) + (fhalf << 4) + c4];
        }
        const float4* x4 = (const float4*)(x + ((b << 10) + n0) * FIN);
        #pragma unroll
        for (int s = 0; s < 2; s++) {
            int idx = t + (s << 8);
            int row = idx >> 4, c4 = idx & 15;
            *(float4*)(sx + row * 68 + (c4 << 2)) = x4[idx];
        }
        if (t < 64) ((float4*)sa)[t] = ((const float4*)a)[t];
    }
    __syncthreads();

    int rg = t >> 4;
    int ci = t & 15;
    int r0 = rg << 1;
    int c0 = ci << 2;
    unsigned long long a0[2], a1[2];
    a0[0] = a0[1] = a1[0] = a1[1] = 0ull;
    {
        const float* x0p = sx + r0 * 68;
        const float* x1p = x0p + 68;
        #pragma unroll 8
        for (int k = 0; k < FIN; k++) {
            float xv0 = x0p[k], xv1 = x1p[k];
            unsigned long long xx0, xx1;
            asm("mov.b64 %0, {%1, %1};" : "=l"(xx0) : "f"(xv0));
            asm("mov.b64 %0, {%1, %1};" : "=l"(xx1) : "f"(xv1));
            const unsigned long long* wp = (const unsigned long long*)(sW + k * 68 + c0);
            #pragma unroll
            for (int q = 0; q < 2; q++) {
                unsigned long long wv = wp[q];
                asm("fma.rn.f32x2 %0, %1, %2, %0;" : "+l"(a0[q]) : "l"(xx0), "l"(wv));
                asm("fma.rn.f32x2 %0, %1, %2, %0;" : "+l"(a1[q]) : "l"(xx1), "l"(wv));
            }
        }
    }
    float f0[4], f1[4];
    #pragma unroll
    for (int q = 0; q < 2; q++) {
        asm("mov.b64 {%0, %1}, %2;" : "=f"(f0[2*q]), "=f"(f0[2*q+1]) : "l"(a0[q]));
        asm("mov.b64 {%0, %1}, %2;" : "=f"(f1[2*q]), "=f"(f1[2*q+1]) : "l"(a1[q]));
    }

    {
        int hl = ci >> 3;
        int head = (fhalf << 1) + hl;
        int dbase = (ci & 7) << 2;
        const float* ap = sa + head * 64;
        const float* aq = ap + 32;
        float ps0 = 0.f, pd0 = 0.f, ps1 = 0.f, pd1 = 0.f;
        #pragma unroll
        for (int cc = 0; cc < 4; cc++) {
            float w1 = ap[dbase + cc], w2 = aq[dbase + cc];
            ps0 = fmaf(f0[cc], w1, ps0); pd0 = fmaf(f0[cc], w2, pd0);
            ps1 = fmaf(f1[cc], w1, ps1); pd1 = fmaf(f1[cc], w2, pd1);
        }
        ps0 += __shfl_xor_sync(0xffffffffu, ps0, 1); ps0 += __shfl_xor_sync(0xffffffffu, ps0, 2);
        ps0 += __shfl_xor_sync(0xffffffffu, ps0, 4);
        pd0 += __shfl_xor_sync(0xffffffffu, pd0, 1); pd0 += __shfl_xor_sync(0xffffffffu, pd0, 2);
        pd0 += __shfl_xor_sync(0xffffffffu, pd0, 4);
        ps1 += __shfl_xor_sync(0xffffffffu, ps1, 1); ps1 += __shfl_xor_sync(0xffffffffu, ps1, 2);
        ps1 += __shfl_xor_sync(0xffffffffu, ps1, 4);
        pd1 += __shfl_xor_sync(0xffffffffu, pd1, 1); pd1 += __shfl_xor_sync(0xffffffffu, pd1, 2);
        pd1 += __shfl_xor_sync(0xffffffffu, pd1, 4);
        if ((ci & 7) == 0) {
            int gnr = (b << 10) + n0 + r0;
            g_src[gnr * HH + head]        = ps0 * LOG2E;
            g_dst[gnr * HH + head]        = pd0 * LOG2E;
            g_src[(gnr + 1) * HH + head]  = ps1 * LOG2E;
            g_dst[(gnr + 1) * HH + head]  = pd1 * LOG2E;
        }
    }

    {
        union { __half2 h2[2]; uint2 v; } u0, u1;
        #pragma unroll
        for (int q = 0; q < 2; q++) {
            u0.h2[q] = __floats2half2_rn(f0[2*q], f0[2*q+1]);
            u1.h2[q] = __floats2half2_rn(f1[2*q], f1[2*q+1]);
        }
        *(uint2*)(sh + r0 * 72 + c0)       = u0.v;
        *(uint2*)(sh + (r0 + 1) * 72 + c0) = u1.v;
    }
    __syncthreads();

    {
        int f_local = t >> 2, hseg = t & 3;
        int f = (fhalf << 6) + f_local;
        union { __half h[8]; uint4 v; } u;
        #pragma unroll
        for (int k2 = 0; k2 < 8; k2++) {
            int j = 2 * hseg + ((k2 >> 1) << 3) + (k2 & 1);
            u.h[k2] = sh[j * 72 + f_local];
        }
        size_t gbase = (((size_t)(b << 7) + f) << 10) + n0 + (hseg << 3);
        *(uint4*)(g_hT + gbase) = u.v;
    }
}

// ---------------- Kernel A: denominators + q store (fragment-permuted fp16) ----------------
__global__ __launch_bounds__(256) void gat_kA(
    const int* __restrict__ adj, const float* __restrict__ ew)
{
    __shared__ float s_srcA[128];
    int b = blockIdx.y, z = blockIdx.z, it = blockIdx.x;
    int i0 = it << 5;
    int jbase = z << 9;
    int t = threadIdx.x, w = t >> 5, lane = t & 31;

    if (t < 128) s_srcA[t] = g_src[((b << 10) + i0) * 4 + t];
    __syncthreads();

    const float4* gd4 = (const float4*)g_dst + (b << 10) + jbase;
    int qgrp = lane >> 4, qk2 = lane & 15;
    int qoff = (qgrp << 5) + ((((qk2 & 3) << 2) + (qk2 >> 2)) << 1);
    __half* qt = g_q + ((((size_t)b * 2 + z) * 32 + it) << 16);

    #pragma unroll
    for (int rr = 0; rr < 4; rr++) {
        int i = w + (rr << 3);
        int gi = i0 + i;
        const int*   adjrow = adj + (size_t)gi * NN + jbase;
        const float* ewrow  = ew  + (size_t)gi * NN + jbase;
        float s0 = s_srcA[i*4+0], s1 = s_srcA[i*4+1], s2 = s_srcA[i*4+2], s3 = s_srcA[i*4+3];
        float l0 = 0.f, l1 = 0.f, l2 = 0.f, l3 = 0.f;
        #pragma unroll 4
        for (int jj = 0; jj < 8; jj++) {
            int j = (lane << 1) + (jj << 6);
            int2 av = __ldg((const int2*)(adjrow + j));
            float2 ew2 = __ldg((const float2*)(ewrow + j));
            float ma = av.x ? 1.f : 0.f;
            float mb = av.y ? 1.f : 0.f;
            float4 dA = __ldg(gd4 + j);
            float4 dB = __ldg(gd4 + j + 1);
            __half* qrow = qt + (jj << 6) + qoff + ((size_t)i << 9);
            float e, qa, qb;
            e = s0 + dA.x; e = fmaxf(e, 0.2f*e); qa = ex2f(e) * ma;
            e = s0 + dB.x; e = fmaxf(e, 0.2f*e); qb = ex2f(e) * mb;
            l0 += qa + qb;
            *(__half2*)(qrow)               = __floats2half2_rn(qa * ew2.x, qb * ew2.y);
            e = s1 + dA.y; e = fmaxf(e, 0.2f*e); qa = ex2f(e) * ma;
            e = s1 + dB.y; e = fmaxf(e, 0.2f*e); qb = ex2f(e) * mb;
            l1 += qa + qb;
            *(__half2*)(qrow + (32 << 9))   = __floats2half2_rn(qa * ew2.x, qb * ew2.y);
            e = s2 + dA.z; e = fmaxf(e, 0.2f*e); qa = ex2f(e) * ma;
            e = s2 + dB.z; e = fmaxf(e, 0.2f*e); qb = ex2f(e) * mb;
            l2 += qa + qb;
            *(__half2*)(qrow + (64 << 9))   = __floats2half2_rn(qa * ew2.x, qb * ew2.y);
            e = s3 + dA.w; e = fmaxf(e, 0.2f*e); qa = ex2f(e) * ma;
            e = s3 + dB.w; e = fmaxf(e, 0.2f*e); qb = ex2f(e) * mb;
            l3 += qa + qb;
            *(__half2*)(qrow + (96 << 9))   = __floats2half2_rn(qa * ew2.x, qb * ew2.y);
        }
        #pragma unroll
        for (int off = 16; off; off >>= 1) {
            l0 += __shfl_xor_sync(0xffffffffu, l0, off);
            l1 += __shfl_xor_sync(0xffffffffu, l1, off);
            l2 += __shfl_xor_sync(0xffffffffu, l2, off);
            l3 += __shfl_xor_sync(0xffffffffu, l3, off);
        }
        if (lane == 0) {
            float* lp = g_lpart + ((size_t)(z * BB + b) << 12) + ((size_t)gi << 2);
            lp[0] = l0; lp[1] = l1; lp[2] = l2; lp[3] = l3;
        }
    }
}

// ---------------- Kernel B: stage q+h, avg, HMMA, atomic out ----------------
#define RSTR 96
#define S_HB    24576
#define S_LINV  49152
#define S_EMPTY 49664
#define SMEMB   49792

__global__ __launch_bounds__(256, 4) void gat_kB(
    const float* __restrict__ ew, float* __restrict__ out, float* __restrict__ avg)
{
    extern __shared__ char smem[];
    __half* s_qA    = (__half*)smem;
    __half* s_hB    = (__half*)(smem + S_HB);
    float*  s_linv  = (float*)(smem + S_LINV);
    int*    s_empty = (int*)(smem + S_EMPTY);

    int b  = blockIdx.y, z = blockIdx.z;
    int i0 = blockIdx.x * TI;
    int t = threadIdx.x, w = t >> 5, lane = t & 31;

    if (t < 128) {
        size_t off = ((size_t)b << 12) + (((size_t)i0) << 2) + t;
        float l = g_lpart[off] + g_lpart[((size_t)BB << 12) + off];
        int emp = !(l > 0.f);
        s_linv[t] = emp ? 1.f : 1.f / l;
        if ((t & 3) == 0) s_empty[t >> 2] = emp;
    }
    __syncthreads();

    float dA0[4] = {0,0,0,0}, dA1[4] = {0,0,0,0};
    float dB0[4] = {0,0,0,0}, dB1[4] = {0,0,0,0};
    int h  = w >> 1;
    int nh = w & 1;
    int g  = lane >> 2;
    int tq = lane & 3;
    int ncol = (h << 5) + (nh << 4);

    int qgrp = lane >> 4, qk2 = lane & 15;
    int qoff = (qgrp << 5) + ((((qk2 & 3) << 2) + (qk2 >> 2)) << 1);

    const __half* qt = g_q + ((((size_t)b * 2 + z) * 32 + blockIdx.x) << 16);

    for (int cl = 0; cl < 8; cl++) {
        int c = (z << 3) + cl;
        __syncthreads();   // prev mma done reading s_qA/s_hB

        // stage h-tile and q-tile gmem -> smem
        #pragma unroll
        for (int s = 0; s < 4; s++) {
            int idx = t + (s << 8);
            int f = idx >> 3, seg = idx & 7;
            *(uint4*)(s_hB + f * RSTR + (seg << 3)) =
                __ldg((const uint4*)(g_hT + (((size_t)(b << 7) + f) << 10) + (c << 6) + (seg << 3)));
        }
        #pragma unroll
        for (int s = 0; s < 4; s++) {
            int idx = t + (s << 8);
            int hi = idx >> 3, seg = idx & 7;     // hi = h*32+i (0..127)
            *(uint4*)(s_qA + hi * RSTR + (seg << 3)) =
                __ldg((const uint4*)(qt + ((size_t)hi << 9) + (cl << 6) + (seg << 3)));
        }
        __syncthreads();

        // avg (+ rare empty patch before the mma sync)
        #pragma unroll
        for (int rr = 0; rr < 4; rr++) {
            int i = w + (rr << 3);
            int gi = i0 + i;
            unsigned qv[4];
            #pragma unroll
            for (int hh = 0; hh < 4; hh++)
                qv[hh] = *(unsigned*)(s_qA + ((hh << 5) + i) * RSTR + qoff);
            if (s_empty[i]) {   // warp-uniform; probability ~0, correctness path
                int jg0 = (c << 6) + (lane << 1);
                float2 ew2 = __ldg((const float2*)(ew + (size_t)gi * NN + jg0));
                __half2 p = __floats2half2_rn(ew2.x * (1.f/1024.f), ew2.y * (1.f/1024.f));
                unsigned pu = *reinterpret_cast<unsigned*>(&p);
                #pragma unroll
                for (int hh = 0; hh < 4; hh++) {
                    *(unsigned*)(s_qA + ((hh << 5) + i) * RSTR + qoff) = pu;
                    qv[hh] = pu;
                }
            }
            float va = 0.f, vb = 0.f;
            #pragma unroll
            for (int hh = 0; hh < 4; hh++) {
                __half2 hv = *reinterpret_cast<__half2*>(&qv[hh]);
                float2 f = __half22float2(hv);
                float lv = s_linv[(i << 2) + hh];
                va = fmaf(f.x, lv, va);
                vb = fmaf(f.y, lv, vb);
            }
            int jg = (c << 6) + (lane << 1);
            *(float2*)(avg + ((size_t)(b * NN) + gi) * NN + jg) =
                make_float2(0.25f * va, 0.25f * vb);
        }
        __syncthreads();

        // HMMA
        #pragma unroll
        for (int ktt = 0; ktt < 2; ktt++) {
            int fo = (ktt << 5) + (tq << 3);
            uint4 aT0g  = *(uint4*)(s_qA + ((h << 5) + g)          * RSTR + fo);
            uint4 aT0g8 = *(uint4*)(s_qA + ((h << 5) + g + 8)      * RSTR + fo);
            uint4 aT1g  = *(uint4*)(s_qA + ((h << 5) + 16 + g)     * RSTR + fo);
            uint4 aT1g8 = *(uint4*)(s_qA + ((h << 5) + 16 + g + 8) * RSTR + fo);
            uint4 bh0 = *(uint4*)(s_hB + (ncol + g)     * RSTR + fo);
            uint4 bh1 = *(uint4*)(s_hB + (ncol + g + 8) * RSTR + fo);
            mma16816(dA0, aT0g.x, aT0g8.x, aT0g.y, aT0g8.y, bh0.x, bh0.y);
            mma16816(dA1, aT0g.x, aT0g8.x, aT0g.y, aT0g8.y, bh1.x, bh1.y);
            mma16816(dB0, aT1g.x, aT1g8.x, aT1g.y, aT1g8.y, bh0.x, bh0.y);
            mma16816(dB1, aT1g.x, aT1g8.x, aT1g.y, aT1g8.y, bh1.x, bh1.y);
            mma16816(dA0, aT0g.z, aT0g8.z, aT0g.w, aT0g8.w, bh0.z, bh0.w);
            mma16816(dA1, aT0g.z, aT0g8.z, aT0g.w, aT0g8.w, bh1.z, bh1.w);
            mma16816(dB0, aT1g.z, aT1g8.z, aT1g.w, aT1g8.w, bh0.z, bh0.w);
            mma16816(dB1, aT1g.z, aT1g8.z, aT1g.w, aT1g8.w, bh1.z, bh1.w);
        }
    }

    // epilogue: normalize + atomic-accumulate (out pre-zeroed by k1; 2 adds per element)
    {
        int col = ncol + (tq << 1);
        float li0  = s_linv[g * 4 + h];
        float li8  = s_linv[(g + 8) * 4 + h];
        float li16 = s_linv[(16 + g) * 4 + h];
        float li24 = s_linv[(24 + g) * 4 + h];
        size_t r0  = ((size_t)((b << 10) + i0 + g)) << 7;
        float* o0 = out + r0 + col;
        atomicAdd(o0,     dA0[0]*li0);  atomicAdd(o0 + 1,  dA0[1]*li0);
        atomicAdd(o0 + 8, dA1[0]*li0);  atomicAdd(o0 + 9,  dA1[1]*li0);
        float* o8 = out + r0 + (8 << 7) + col;
        atomicAdd(o8,     dA0[2]*li8);  atomicAdd(o8 + 1,  dA0[3]*li8);
        atomicAdd(o8 + 8, dA1[2]*li8);  atomicAdd(o8 + 9,  dA1[3]*li8);
        float* o16 = out + r0 + (16 << 7) + col;
        atomicAdd(o16,     dB0[0]*li16); atomicAdd(o16 + 1, dB0[1]*li16);
        atomicAdd(o16 + 8, dB1[0]*li16); atomicAdd(o16 + 9, dB1[1]*li16);
        float* o24 = out + r0 + (24 << 7) + col;
        atomicAdd(o24,     dB0[2]*li24); atomicAdd(o24 + 1, dB0[3]*li24);
        atomicAdd(o24 + 8, dB1[2]*li24); atomicAdd(o24 + 9, dB1[3]*li24);
    }
}

extern "C" void kernel_launch(void* const* d_in, const int* in_sizes, int n_in,
                              void* d_out, int out_size)
{
    (void)in_sizes; (void)n_in; (void)out_size;
    const float* x   = (const float*)d_in[0];
    const int*   adj = (const int*)d_in[1];
    const float* ew  = (const float*)d_in[2];
    const float* W   = (const float*)d_in[3];
    const float* a   = (const float*)d_in[4];
    float* out = (float*)d_out;                   // [B,N,128]
    float* avg = out + (size_t)BB * NN * FOUT;    // [B,N,N]

    cudaFuncSetAttribute(gat_kB, cudaFuncAttributeMaxDynamicSharedMemorySize, SMEMB);

    gat_k1<<<BB * 32 * 2, 256>>>(x, W, a, out);
    gat_kA<<<dim3(NN / 32, BB, 2), 256>>>(adj, ew);
    gat_kB<<<dim3(NN / TI, BB, 2), 256, SMEMB>>>(ew, out, avg);
}

// round 14
// speedup vs baseline: 1.0568x; 1.0568x over previous
#include <cuda_runtime.h>
#include <cuda_fp16.h>
#include <cstdint>

#define BB 8
#define NN 1024
#define FIN 64
#define FOUT 128
#define HH 4
#define DD 32
#define TI 32
#define LOG2E 1.4426950408889634f

// device-global scratch. Transposed + permuted h: [b][f][j_perm], fp16.
// Within each 32-node group, slot s holds node j = 2*(s>>3) + (((s&7)>>1)<<3) + (s&1).
__device__ __align__(16) __half g_hT[BB * FOUT * NN];
__device__ float g_src[BB * NN * HH];           // pre-scaled by log2e
__device__ float g_dst[BB * NN * HH];
__device__ float g_lpart[2 * BB * NN * HH];     // partial softmax denominators

__device__ __forceinline__ float ex2f(float x) {
    float r;
    asm("ex2.approx.ftz.f32 %0, %1;" : "=f"(r) : "f"(x));
    return r;
}
__device__ __forceinline__ void mma16816(float* d, unsigned a0, unsigned a1,
                                         unsigned a2, unsigned a3,
                                         unsigned b0, unsigned b1) {
    asm volatile(
        "mma.sync.aligned.m16n8k16.row.col.f32.f16.f16.f32 "
        "{%0,%1,%2,%3},{%4,%5,%6,%7},{%8,%9},{%0,%1,%2,%3};"
        : "+f"(d[0]), "+f"(d[1]), "+f"(d[2]), "+f"(d[3])
        : "r"(a0), "r"(a1), "r"(a2), "r"(a3), "r"(b0), "r"(b1));
}

// ---------------- Kernel 0: src/dst logits via WA = W·a (64x8), then x·WA ----------------
// grid 64 blocks x 256 threads; block = 128 rows of x (flattened b*N+n).
__global__ __launch_bounds__(256) void gat_k0(
    const float* __restrict__ x, const float* __restrict__ W, const float* __restrict__ a)
{
    __shared__ float sWA[64][8];     // [k][half*4+h]
    __shared__ float sx[128 * 68];   // padded rows

    int t = threadIdx.x;
    int rbase = blockIdx.x << 7;

    // WA: entry e = (k, half, h); 512 entries, 2 per thread
    #pragma unroll
    for (int e = t; e < 512; e += 256) {
        int k = e >> 3, half = (e >> 2) & 1, h = e & 3;
        const float* wrow = W + (k << 7) + (h << 5);
        const float* arow = a + (h << 6) + (half << 5);
        float s = 0.f;
        #pragma unroll
        for (int d = 0; d < 32; d++) s = fmaf(__ldg(wrow + d), __ldg(arow + d), s);
        sWA[k][half * 4 + h] = s;
    }
    // stage 128 x-rows (coalesced)
    {
        const float4* x4 = (const float4*)(x + ((size_t)rbase << 6));
        #pragma unroll
        for (int s = 0; s < 8; s++) {
            int idx = t + (s << 8);                 // 128 rows x 16 float4
            int row = idx >> 4, c4 = idx & 15;
            *(float4*)(sx + row * 68 + (c4 << 2)) = x4[idx];
        }
    }
    __syncthreads();

    // thread = (row r = t>>1, half = t&1): 4 dots of 64
    int r = t >> 1, half = t & 1;
    const float* xr = sx + r * 68;
    float o0 = 0.f, o1 = 0.f, o2 = 0.f, o3 = 0.f;
    #pragma unroll 8
    for (int k = 0; k < 64; k++) {
        float xv = xr[k];
        const float* wa = &sWA[k][half << 2];
        o0 = fmaf(xv, wa[0], o0);
        o1 = fmaf(xv, wa[1], o1);
        o2 = fmaf(xv, wa[2], o2);
        o3 = fmaf(xv, wa[3], o3);
    }
    int gnr = rbase + r;
    float4 v = make_float4(o0 * LOG2E, o1 * LOG2E, o2 * LOG2E, o3 * LOG2E);
    if (half == 0) *(float4*)(g_src + (gnr << 2)) = v;
    else           *(float4*)(g_dst + (gnr << 2)) = v;
}

// ---------------- Fused kernel: h-GEMM blocks (even) + denominator blocks (odd) ----------------
// grid = 1024 x 256 threads. dyn smem = 30720 bytes (h branch layout).
#define F_SW 0
#define F_SX 17408
#define F_SH 26112
#define SMEMF 30720

__global__ __launch_bounds__(256) void gat_k1A(
    const float* __restrict__ x, const float* __restrict__ W,
    const int* __restrict__ adj, float* __restrict__ out)
{
    extern __shared__ char fsm[];
    int t = threadIdx.x;

    if ((blockIdx.x & 1) == 0) {
        // ---------------- h-GEMM branch (R12 gat_k1 minus src/dst) ----------------
        float* sW  = (float*)(fsm + F_SW);     // 64 x 68
        float* sx  = (float*)(fsm + F_SX);     // 32 x 68
        __half* sh = (__half*)(fsm + F_SH);    // 32 x 72

        int hb    = blockIdx.x >> 1;
        int b     = hb >> 6;
        int n0    = ((hb >> 1) & 31) << 5;
        int fhalf = hb & 1;

        // zero out: 512 h-blocks x 256 threads x 2 float4 = 4MB
        {
            float4 z = make_float4(0.f, 0.f, 0.f, 0.f);
            size_t o4 = ((size_t)hb * 256 + t) * 2;
            ((float4*)out)[o4]     = z;
            ((float4*)out)[o4 + 1] = z;
        }

        {
            const float4* W4 = (const float4*)W;
            #pragma unroll
            for (int s = 0; s < 4; s++) {
                int idx = t + (s << 8);
                int row = idx >> 4, c4 = idx & 15;
                *(float4*)(sW + row * 68 + (c4 << 2)) = W4[(row << 5) + (fhalf << 4) + c4];
            }
            const float4* x4 = (const float4*)(x + ((b << 10) + n0) * FIN);
            #pragma unroll
            for (int s = 0; s < 2; s++) {
                int idx = t + (s << 8);
                int row = idx >> 4, c4 = idx & 15;
                *(float4*)(sx + row * 68 + (c4 << 2)) = x4[idx];
            }
        }
        __syncthreads();

        int rg = t >> 4;
        int ci = t & 15;
        int r0 = rg << 1;
        int c0 = ci << 2;
        unsigned long long a0[2], a1[2];
        a0[0] = a0[1] = a1[0] = a1[1] = 0ull;
        {
            const float* x0p = sx + r0 * 68;
            const float* x1p = x0p + 68;
            #pragma unroll 8
            for (int k = 0; k < FIN; k++) {
                float xv0 = x0p[k], xv1 = x1p[k];
                unsigned long long xx0, xx1;
                asm("mov.b64 %0, {%1, %1};" : "=l"(xx0) : "f"(xv0));
                asm("mov.b64 %0, {%1, %1};" : "=l"(xx1) : "f"(xv1));
                const unsigned long long* wp = (const unsigned long long*)(sW + k * 68 + c0);
                #pragma unroll
                for (int q = 0; q < 2; q++) {
                    unsigned long long wv = wp[q];
                    asm("fma.rn.f32x2 %0, %1, %2, %0;" : "+l"(a0[q]) : "l"(xx0), "l"(wv));
                    asm("fma.rn.f32x2 %0, %1, %2, %0;" : "+l"(a1[q]) : "l"(xx1), "l"(wv));
                }
            }
        }
        float f0[4], f1[4];
        #pragma unroll
        for (int q = 0; q < 2; q++) {
            asm("mov.b64 {%0, %1}, %2;" : "=f"(f0[2*q]), "=f"(f0[2*q+1]) : "l"(a0[q]));
            asm("mov.b64 {%0, %1}, %2;" : "=f"(f1[2*q]), "=f"(f1[2*q+1]) : "l"(a1[q]));
        }

        {
            union { __half2 h2[2]; uint2 v; } u0, u1;
            #pragma unroll
            for (int q = 0; q < 2; q++) {
                u0.h2[q] = __floats2half2_rn(f0[2*q], f0[2*q+1]);
                u1.h2[q] = __floats2half2_rn(f1[2*q], f1[2*q+1]);
            }
            *(uint2*)(sh + r0 * 72 + c0)       = u0.v;
            *(uint2*)(sh + (r0 + 1) * 72 + c0) = u1.v;
        }
        __syncthreads();

        {
            int f_local = t >> 2, hseg = t & 3;
            int f = (fhalf << 6) + f_local;
            union { __half h[8]; uint4 v; } u;
            #pragma unroll
            for (int k2 = 0; k2 < 8; k2++) {
                int j = 2 * hseg + ((k2 >> 1) << 3) + (k2 & 1);
                u.h[k2] = sh[j * 72 + f_local];
            }
            size_t gbase = (((size_t)(b << 7) + f) << 10) + n0 + (hseg << 3);
            *(uint4*)(g_hT + gbase) = u.v;
        }
    } else {
        // ---------------- denominator branch (R12 gat_kA verbatim, decoded ids) ----------------
        float* s_srcA = (float*)fsm;           // 128 floats
        int ab = blockIdx.x >> 1;              // 0..511
        int it = ab & 31;
        int b  = (ab >> 5) & 7;
        int z  = ab >> 8;
        int i0 = it << 5;
        int jbase = z << 9;
        int w = t >> 5, lane = t & 31;

        if (t < 128) s_srcA[t] = g_src[((b << 10) + i0) * 4 + t];
        __syncthreads();

        const float4* gd4 = (const float4*)g_dst + (b << 10) + jbase;

        #pragma unroll
        for (int rr = 0; rr < 4; rr++) {
            int i = w + (rr << 3);
            int gi = i0 + i;
            const int* adjrow = adj + (size_t)gi * NN + jbase;
            float s0 = s_srcA[i*4+0], s1 = s_srcA[i*4+1], s2 = s_srcA[i*4+2], s3 = s_srcA[i*4+3];
            float l0 = 0.f, l1 = 0.f, l2 = 0.f, l3 = 0.f;
            #pragma unroll 4
            for (int jj = 0; jj < 8; jj++) {
                int j = (lane << 1) + (jj << 6);
                int2 av = __ldg((const int2*)(adjrow + j));
                float ma = av.x ? 1.f : 0.f;
                float mb = av.y ? 1.f : 0.f;
                float4 dA = __ldg(gd4 + j);
                float4 dB = __ldg(gd4 + j + 1);
                float e;
                e = s0 + dA.x; e = fmaxf(e, 0.2f*e); l0 = fmaf(ex2f(e), ma, l0);
                e = s1 + dA.y; e = fmaxf(e, 0.2f*e); l1 = fmaf(ex2f(e), ma, l1);
                e = s2 + dA.z; e = fmaxf(e, 0.2f*e); l2 = fmaf(ex2f(e), ma, l2);
                e = s3 + dA.w; e = fmaxf(e, 0.2f*e); l3 = fmaf(ex2f(e), ma, l3);
                e = s0 + dB.x; e = fmaxf(e, 0.2f*e); l0 = fmaf(ex2f(e), mb, l0);
                e = s1 + dB.y; e = fmaxf(e, 0.2f*e); l1 = fmaf(ex2f(e), mb, l1);
                e = s2 + dB.z; e = fmaxf(e, 0.2f*e); l2 = fmaf(ex2f(e), mb, l2);
                e = s3 + dB.w; e = fmaxf(e, 0.2f*e); l3 = fmaf(ex2f(e), mb, l3);
            }
            #pragma unroll
            for (int off = 16; off; off >>= 1) {
                l0 += __shfl_xor_sync(0xffffffffu, l0, off);
                l1 += __shfl_xor_sync(0xffffffffu, l1, off);
                l2 += __shfl_xor_sync(0xffffffffu, l2, off);
                l3 += __shfl_xor_sync(0xffffffffu, l3, off);
            }
            if (lane == 0) {
                float* lp = g_lpart + ((size_t)(z * BB + b) << 12) + ((size_t)gi << 2);
                lp[0] = l0; lp[1] = l1; lp[2] = l2; lp[3] = l3;
            }
        }
    }
}

// ---------------- Kernel B: q + avg + HMMA on one j-half, atomic out (R12 verbatim) ----------------
#define RSTR 96
#define S_HB    24576
#define S_SRC   49152
#define S_LINV  49664
#define S_EMPTY 50176
#define SMEMB   50304

__global__ __launch_bounds__(256, 4) void gat_kB(
    const int* __restrict__ adj, const float* __restrict__ ew,
    float* __restrict__ out, float* __restrict__ avg)
{
    extern __shared__ char smem[];
    __half* s_qA    = (__half*)smem;
    __half* s_hB    = (__half*)(smem + S_HB);
    float*  s_src   = (float*)(smem + S_SRC);
    float*  s_linv  = (float*)(smem + S_LINV);
    int*    s_empty = (int*)(smem + S_EMPTY);

    int b  = blockIdx.y, z = blockIdx.z;
    int i0 = blockIdx.x * TI;
    int t = threadIdx.x, w = t >> 5, lane = t & 31;

    if (t < 128) {
        s_src[t] = g_src[((b << 10) + i0) * 4 + t];
        size_t off = ((size_t)b << 12) + (((size_t)i0) << 2) + t;
        float l = g_lpart[off] + g_lpart[((size_t)BB << 12) + off];
        int emp = !(l > 0.f);
        s_linv[t] = emp ? 1.f : 1.f / l;
        if ((t & 3) == 0) s_empty[t >> 2] = emp;
    }
    __syncthreads();

    float dA0[4] = {0,0,0,0}, dA1[4] = {0,0,0,0};
    float dB0[4] = {0,0,0,0}, dB1[4] = {0,0,0,0};
    int h  = w >> 1;
    int nh = w & 1;
    int g  = lane >> 2;
    int tq = lane & 3;
    int ncol = (h << 5) + (nh << 4);

    int qgrp = lane >> 4, qk2 = lane & 15;
    int qoff = (qgrp << 5) + ((((qk2 & 3) << 2) + (qk2 >> 2)) << 1);

    const float4* gd4 = (const float4*)g_dst + (b << 10);

    for (int cl = 0; cl < 8; cl++) {
        int c = (z << 3) + cl;
        __syncthreads();

        #pragma unroll
        for (int s = 0; s < 4; s++) {
            int idx = t + (s << 8);
            int f = idx >> 3, seg = idx & 7;
            *(uint4*)(s_hB + f * RSTR + (seg << 3)) =
                __ldg((const uint4*)(g_hT + (((size_t)(b << 7) + f) << 10) + (c << 6) + (seg << 3)));
        }

        #pragma unroll
        for (int rr = 0; rr < 4; rr++) {
            int i = w + (rr << 3);
            int gi = i0 + i;
            const int*   adjrow = adj + (size_t)gi * NN;
            const float* ewrow  = ew  + (size_t)gi * NN;
            float* avgrow = avg + ((size_t)(b * NN) + gi) * NN;
            float sv[4], lv[4];
            #pragma unroll
            for (int q = 0; q < 4; q++) { sv[q] = s_src[i*4+q]; lv[q] = s_linv[i*4+q]; }
            int emp = s_empty[i];
            int jl = lane << 1;
            int j  = (c << 6) + jl;
            int2   av  = __ldg((const int2*)(adjrow + j));
            float2 ew2 = __ldg((const float2*)(ewrow + j));
            float4 dA = __ldg(gd4 + j);
            float4 dB = __ldg(gd4 + j + 1);
            float ma = av.x ? 1.f : 0.f;
            float mb = av.y ? 1.f : 0.f;
            float dAv[4] = {dA.x, dA.y, dA.z, dA.w};
            float dBv[4] = {dB.x, dB.y, dB.z, dB.w};
            float va = 0.f, vb = 0.f;
            #pragma unroll
            for (int hh = 0; hh < 4; hh++) {
                float e, qa, qb;
                e = sv[hh] + dAv[hh]; e = fmaxf(e, 0.2f*e); qa = ex2f(e) * ma;
                e = sv[hh] + dBv[hh]; e = fmaxf(e, 0.2f*e); qb = ex2f(e) * mb;
                qa = emp ? (1.f / 1024.f) : qa;
                qb = emp ? (1.f / 1024.f) : qb;
                va = fmaf(qa, lv[hh], va);
                vb = fmaf(qb, lv[hh], vb);
                __half2 hq = __floats2half2_rn(qa * ew2.x, qb * ew2.y);
                *(__half2*)(s_qA + ((hh << 5) + i) * RSTR + qoff) = hq;
            }
            *(float2*)(avgrow + j) = make_float2(0.25f * va * ew2.x, 0.25f * vb * ew2.y);
        }
        __syncthreads();

        #pragma unroll
        for (int ktt = 0; ktt < 2; ktt++) {
            int fo = (ktt << 5) + (tq << 3);
            uint4 aT0g  = *(uint4*)(s_qA + ((h << 5) + g)          * RSTR + fo);
            uint4 aT0g8 = *(uint4*)(s_qA + ((h << 5) + g + 8)      * RSTR + fo);
            uint4 aT1g  = *(uint4*)(s_qA + ((h << 5) + 16 + g)     * RSTR + fo);
            uint4 aT1g8 = *(uint4*)(s_qA + ((h << 5) + 16 + g + 8) * RSTR + fo);
            uint4 bh0 = *(uint4*)(s_hB + (ncol + g)     * RSTR + fo);
            uint4 bh1 = *(uint4*)(s_hB + (ncol + g + 8) * RSTR + fo);
            mma16816(dA0, aT0g.x, aT0g8.x, aT0g.y, aT0g8.y, bh0.x, bh0.y);
            mma16816(dA1, aT0g.x, aT0g8.x, aT0g.y, aT0g8.y, bh1.x, bh1.y);
            mma16816(dB0, aT1g.x, aT1g8.x, aT1g.y, aT1g8.y, bh0.x, bh0.y);
            mma16816(dB1, aT1g.x, aT1g8.x, aT1g.y, aT1g8.y, bh1.x, bh1.y);
            mma16816(dA0, aT0g.z, aT0g8.z, aT0g.w, aT0g8.w, bh0.z, bh0.w);
            mma16816(dA1, aT0g.z, aT0g8.z, aT0g.w, aT0g8.w, bh1.z, bh1.w);
            mma16816(dB0, aT1g.z, aT1g8.z, aT1g.w, aT1g8.w, bh0.z, bh0.w);
            mma16816(dB1, aT1g.z, aT1g8.z, aT1g.w, aT1g8.w, bh1.z, bh1.w);
        }
    }

    // epilogue: normalize + atomic-accumulate (out pre-zeroed by k1A; 2 adds per element)
    {
        int col = ncol + (tq << 1);
        float li0  = s_linv[g * 4 + h];
        float li8  = s_linv[(g + 8) * 4 + h];
        float li16 = s_linv[(16 + g) * 4 + h];
        float li24 = s_linv[(24 + g) * 4 + h];
        size_t r0  = ((size_t)((b << 10) + i0 + g)) << 7;
        float* o0 = out + r0 + col;
        atomicAdd(o0,     dA0[0]*li0);  atomicAdd(o0 + 1,  dA0[1]*li0);
        atomicAdd(o0 + 8, dA1[0]*li0);  atomicAdd(o0 + 9,  dA1[1]*li0);
        float* o8 = out + r0 + (8 << 7) + col;
        atomicAdd(o8,     dA0[2]*li8);  atomicAdd(o8 + 1,  dA0[3]*li8);
        atomicAdd(o8 + 8, dA1[2]*li8);  atomicAdd(o8 + 9,  dA1[3]*li8);
        float* o16 = out + r0 + (16 << 7) + col;
        atomicAdd(o16,     dB0[0]*li16); atomicAdd(o16 + 1, dB0[1]*li16);
        atomicAdd(o16 + 8, dB1[0]*li16); atomicAdd(o16 + 9, dB1[1]*li16);
        float* o24 = out + r0 + (24 << 7) + col;
        atomicAdd(o24,     dB0[2]*li24); atomicAdd(o24 + 1, dB0[3]*li24);
        atomicAdd(o24 + 8, dB1[2]*li24); atomicAdd(o24 + 9, dB1[3]*li24);
    }
}

extern "C" void kernel_launch(void* const* d_in, const int* in_sizes, int n_in,
                              void* d_out, int out_size)
{
    (void)in_sizes; (void)n_in; (void)out_size;
    const float* x   = (const float*)d_in[0];
    const int*   adj = (const int*)d_in[1];
    const float* ew  = (const float*)d_in[2];
    const float* W   = (const float*)d_in[3];
    const float* a   = (const float*)d_in[4];
    float* out = (float*)d_out;                   // [B,N,128]
    float* avg = out + (size_t)BB * NN * FOUT;    // [B,N,N]

    cudaFuncSetAttribute(gat_kB, cudaFuncAttributeMaxDynamicSharedMemorySize, SMEMB);

    gat_k0<<<64, 256>>>(x, W, a);
    gat_k1A<<<1024, 256, SMEMF>>>(x, W, adj, out);
    gat_kB<<<dim3(NN / TI, BB, 2), 256, SMEMB>>>(adj, ew, out, avg);
}